// round 1
// baseline (speedup 1.0000x reference)
#include <cuda_runtime.h>
#include <cuda_bf16.h>
#include <cstdint>

// Problem constants (fixed by the reference)
#define M_DIM 8192
#define N_DIM 8192
#define C_DIM 80

// Scratch (no allocations allowed) — transposed pre_cls and row softplus-sums
__device__ float g_T[C_DIM * N_DIM];     // g_T[c*N + n] = pre_cls[n*C + c]
__device__ float g_base[N_DIM];          // base[n] = sum_c softplus(pre_cls[n,c])

// ---------------------------------------------------------------------------
// Kernel A: compute base[n] and transpose pre_cls into g_T.
// One thread per n-row. Reads 2.6 MB, writes 2.6 MB — negligible cost.
// ---------------------------------------------------------------------------
__global__ void base_transpose_kernel(const float* __restrict__ pre)
{
    int n = blockIdx.x * blockDim.x + threadIdx.x;
    if (n >= N_DIM) return;

    const float* row = pre + (size_t)n * C_DIM;
    float s = 0.0f;
#pragma unroll
    for (int c = 0; c < C_DIM; ++c) {
        float x = row[c];
        // numerically stable softplus: max(x,0) + log1p(exp(-|x|))
        float sp = fmaxf(x, 0.0f) + log1pf(expf(-fabsf(x)));
        s += sp;
        g_T[(size_t)c * N_DIM + n] = x;   // coalesced across threads for fixed c
    }
    g_base[n] = s;
}

// ---------------------------------------------------------------------------
// Kernel B: out[m,n] = base[n] - T[g[m]][n]
// 256 threads/block, float4 along n (1024 floats per block), MROWS m-rows per
// block so base4 is loaded once and reused. Streaming stores (.cs) keep the
// 256 MB output from polluting L2.
// ---------------------------------------------------------------------------
#define BTHREADS 256
#define MROWS 8
#define N4 (N_DIM / 4)   // 2048 float4 per row

__global__ __launch_bounds__(BTHREADS)
void out_kernel(const int* __restrict__ gt, float4* __restrict__ out)
{
    int n4 = blockIdx.x * BTHREADS + threadIdx.x;   // float4 index along n
    int m0 = blockIdx.y * MROWS;

    __shared__ int sg[MROWS];
    if (threadIdx.x < MROWS) sg[threadIdx.x] = gt[m0 + threadIdx.x];
    __syncthreads();

    const float4 b = ((const float4*)g_base)[n4];

#pragma unroll
    for (int r = 0; r < MROWS; ++r) {
        const float4* Trow = (const float4*)(g_T + (size_t)sg[r] * N_DIM);
        float4 p = __ldg(&Trow[n4]);
        float4 o;
        o.x = b.x - p.x;
        o.y = b.y - p.y;
        o.z = b.z - p.z;
        o.w = b.w - p.w;
        __stcs(&out[(size_t)(m0 + r) * N4 + n4], o);
    }
}

// ---------------------------------------------------------------------------
extern "C" void kernel_launch(void* const* d_in, const int* in_sizes, int n_in,
                              void* d_out, int out_size)
{
    const int*   gt  = (const int*)d_in[0];      // gt_kind_ind [M]
    const float* pre = (const float*)d_in[1];    // pre_cls [N, C]
    float4*      out = (float4*)d_out;           // [M, N] f32

    base_transpose_kernel<<<(N_DIM + 255) / 256, 256>>>(pre);

    dim3 grid(N4 / BTHREADS, M_DIM / MROWS);     // (8, 1024)
    out_kernel<<<grid, BTHREADS>>>(gt, out);
}